// round 1
// baseline (speedup 1.0000x reference)
#include <cuda_runtime.h>
#include <math.h>

// Problem constants (fixed by setup_inputs)
#define BQ    1024        // batch of queries
#define DIM   1024        // query dim
#define CDIM  128         // compressed dim
#define NKEYS 100000
#define KNN   5
#define EPSW  1e-6f
#define CAP   16384       // candidate capacity (expected ~10)

// ---------------- scratch (device globals; no allocations allowed) ---------
__device__ float g_h1[BQ * (DIM / 2)];
__device__ float g_h2[BQ * (DIM / 4)];
__device__ float g_cq[BQ * CDIM];
__device__ float g_qn[BQ];
__device__ int   g_Qmax_bits;          // max ||cq||^2 as float bits (>=0)
__device__ float g_kn[NKEYS];
__device__ float g_tau;
__device__ int   g_cand[CAP];
__device__ int   g_cand_count;
__device__ float g_weighted[BQ * CDIM];
__device__ float g_g1[BQ * (DIM / 4)];
__device__ float g_g2[BQ * (DIM / 2)];

// ---------------- small init ----------------------------------------------
__global__ void init_kernel() {
    g_Qmax_bits  = 0;
    g_cand_count = 0;
}

// ---------------- tiled fp32 GEMM: C = act(A[MxK] * B[KxN] + bias) ---------
// BM=BN=64, BK=16, 256 threads, 4x4 per-thread tile. All dims are multiples
// of the tile sizes for every layer in this problem (no bounds checks).
template <int RELU>
__global__ void sgemm_bias_kernel(const float* __restrict__ A,
                                  const float* __restrict__ Bm,
                                  const float* __restrict__ bias,
                                  float* __restrict__ Cm,
                                  int M, int N, int K) {
    __shared__ float As[16][68];   // stored transposed: As[k][m]
    __shared__ float Bs[16][68];   // Bs[k][n]
    const int tid = threadIdx.x;
    const int tx = tid & 15;       // n direction
    const int ty = tid >> 4;       // m direction
    const int bm = blockIdx.y * 64, bn = blockIdx.x * 64;

    float acc[4][4];
#pragma unroll
    for (int i = 0; i < 4; i++)
#pragma unroll
        for (int j = 0; j < 4; j++) acc[i][j] = 0.f;

    const int ar = tid >> 2;            // 0..63 (m)
    const int ak = (tid & 3) << 2;      // 0,4,8,12 (k)
    const int br = tid >> 4;            // 0..15 (k)
    const int bc = (tid & 15) << 2;     // 0..60 (n)

    for (int k0 = 0; k0 < K; k0 += 16) {
        float4 av = *reinterpret_cast<const float4*>(
            &A[(size_t)(bm + ar) * K + k0 + ak]);
        As[ak + 0][ar] = av.x;
        As[ak + 1][ar] = av.y;
        As[ak + 2][ar] = av.z;
        As[ak + 3][ar] = av.w;
        *reinterpret_cast<float4*>(&Bs[br][bc]) =
            *reinterpret_cast<const float4*>(&Bm[(size_t)(k0 + br) * N + bn + bc]);
        __syncthreads();
#pragma unroll
        for (int kk = 0; kk < 16; kk++) {
            float4 a4 = *reinterpret_cast<const float4*>(&As[kk][ty * 4]);
            float4 b4 = *reinterpret_cast<const float4*>(&Bs[kk][tx * 4]);
            float aa[4] = {a4.x, a4.y, a4.z, a4.w};
            float bb[4] = {b4.x, b4.y, b4.z, b4.w};
#pragma unroll
            for (int i = 0; i < 4; i++)
#pragma unroll
                for (int j = 0; j < 4; j++)
                    acc[i][j] = fmaf(aa[i], bb[j], acc[i][j]);
        }
        __syncthreads();
    }

#pragma unroll
    for (int i = 0; i < 4; i++) {
        float4 out;
        float* o = reinterpret_cast<float*>(&out);
#pragma unroll
        for (int j = 0; j < 4; j++) {
            float v = acc[i][j] + bias[bn + tx * 4 + j];
            if (RELU) v = fmaxf(v, 0.f);
            o[j] = v;
        }
        *reinterpret_cast<float4*>(
            &Cm[(size_t)(bm + ty * 4 + i) * N + bn + tx * 4]) = out;
    }
}

// ---------------- row squared-norms (rows of width 128) --------------------
__global__ void rownorm_kernel(const float* __restrict__ X,
                               float* __restrict__ out, int rows, int do_qmax) {
    int gw = (int)((blockIdx.x * (size_t)blockDim.x + threadIdx.x) >> 5);
    int lane = threadIdx.x & 31;
    if (gw >= rows) return;
    float4 v = reinterpret_cast<const float4*>(X + (size_t)gw * 128)[lane];
    float s = v.x * v.x + v.y * v.y + v.z * v.z + v.w * v.w;
#pragma unroll
    for (int o = 16; o; o >>= 1) s += __shfl_xor_sync(0xffffffffu, s, o);
    if (lane == 0) {
        out[gw] = s;
        if (do_qmax) atomicMax(&g_Qmax_bits, __float_as_int(s));  // s >= 0
    }
}

// ---------------- tau = 5th smallest upper bound + margin ------------------
__global__ void tau_kernel() {
    __shared__ float sv[1024 * 5];
    const int tid = threadIdx.x;
    const float Q = sqrtf(__int_as_float(g_Qmax_bits));
    float t5[5] = {3.4e38f, 3.4e38f, 3.4e38f, 3.4e38f, 3.4e38f};
    for (int n = tid; n < NKEYS; n += 1024) {
        float kn = g_kn[n];
        float u = kn + 2.f * Q * sqrtf(kn) + 1e-3f;
        if (u < t5[4]) {
            int p = 4;
            while (p > 0 && t5[p - 1] > u) { t5[p] = t5[p - 1]; p--; }
            t5[p] = u;
        }
    }
#pragma unroll
    for (int i = 0; i < 5; i++) sv[tid * 5 + i] = t5[i];
    __syncthreads();
    for (int stride = 512; stride >= 1; stride >>= 1) {
        if (tid < stride) {
            float a[5], b[5], m[5];
#pragma unroll
            for (int i = 0; i < 5; i++) {
                a[i] = sv[tid * 5 + i];
                b[i] = sv[(tid + stride) * 5 + i];
            }
            int ia = 0, ib = 0;
#pragma unroll
            for (int i = 0; i < 5; i++) m[i] = (a[ia] <= b[ib]) ? a[ia++] : b[ib++];
#pragma unroll
            for (int i = 0; i < 5; i++) sv[tid * 5 + i] = m[i];
        }
        __syncthreads();
    }
    if (tid == 0) g_tau = sv[4] + 1e-2f;
}

// ---------------- candidate compaction -------------------------------------
__global__ void cand_kernel() {
    int n = blockIdx.x * blockDim.x + threadIdx.x;
    if (n >= NKEYS) return;
    float Q = sqrtf(__int_as_float(g_Qmax_bits));
    float kn = g_kn[n];
    float l = kn - 2.f * Q * sqrtf(kn) - 1e-3f;
    if (l <= g_tau) {
        int p = atomicAdd(&g_cand_count, 1);
        if (p < CAP) g_cand[p] = n;
    }
}

// ---------------- exact rescore + top-5 + weighted gather ------------------
#define CHUNK 1024
__global__ void rescore_kernel(const float* __restrict__ keys,
                               const float* __restrict__ values,
                               float* __restrict__ conf_out) {
    const int b = blockIdx.x;      // one query per block
    const int tid = threadIdx.x;   // 128 threads
    __shared__ float sq[CDIM];
    __shared__ float dv[CHUNK];
    __shared__ int   di[CHUNK];
    __shared__ float rd[KNN];
    __shared__ int   ri[KNN];
    __shared__ float rv[128];
    __shared__ int   rvi[128];
    __shared__ int   rvj[128];
    __shared__ float sw[KNN];

    sq[tid] = g_cq[(size_t)b * CDIM + tid];
    if (tid < KNN) { rd[tid] = 3.4e38f; ri[tid] = 0x7fffffff; }
    int count = g_cand_count;
    if (count > CAP) count = CAP;
    __syncthreads();

    for (int c0 = 0; c0 < count; c0 += CHUNK) {
        int len = min(CHUNK, count - c0);
        for (int j = tid; j < len; j += 128) {
            int n = g_cand[c0 + j];
            const float* kr = keys + (size_t)n * CDIM;
            double acc = 0.0;
#pragma unroll 8
            for (int d = 0; d < CDIM; d++)
                acc += (double)sq[d] * (double)kr[d];
            dv[j] = (float)((double)g_qn[b] + (double)g_kn[n] - 2.0 * acc);
            di[j] = n;
        }
        __syncthreads();
        for (int r = 0; r < KNN; r++) {
            float mv = 3.4e38f; int mi = 0x7fffffff; int mj = -1;
            for (int j = tid; j < len; j += 128) {
                float v = dv[j]; int n = di[j];
                if (v < mv || (v == mv && n < mi)) { mv = v; mi = n; mj = j; }
            }
            rv[tid] = mv; rvi[tid] = mi; rvj[tid] = mj;
            __syncthreads();
            for (int s = 64; s >= 1; s >>= 1) {
                if (tid < s) {
                    if (rv[tid + s] < rv[tid] ||
                        (rv[tid + s] == rv[tid] && rvi[tid + s] < rvi[tid])) {
                        rv[tid] = rv[tid + s];
                        rvi[tid] = rvi[tid + s];
                        rvj[tid] = rvj[tid + s];
                    }
                }
                __syncthreads();
            }
            if (tid == 0 && rvj[0] >= 0) {
                float v = rv[0]; int n = rvi[0];
                if (v < rd[KNN - 1] || (v == rd[KNN - 1] && n < ri[KNN - 1])) {
                    int p = KNN - 1;
                    while (p > 0 && (rd[p - 1] > v ||
                                     (rd[p - 1] == v && ri[p - 1] > n))) {
                        rd[p] = rd[p - 1]; ri[p] = ri[p - 1]; p--;
                    }
                    rd[p] = v; ri[p] = n;
                }
                dv[rvj[0]] = 3.4e38f;  // remove winner from chunk
            }
            __syncthreads();
        }
    }

    if (tid == 0) {
        float w[KNN], ws = 0.f;
#pragma unroll
        for (int j = 0; j < KNN; j++) { w[j] = 1.f / (rd[j] + EPSW); ws += w[j]; }
#pragma unroll
        for (int j = 0; j < KNN; j++) sw[j] = w[j] / ws;
        conf_out[b] = 1.f / (rd[0] + EPSW);
    }
    __syncthreads();

    float acc = 0.f;
#pragma unroll
    for (int j = 0; j < KNN; j++)
        acc += sw[j] * values[(size_t)ri[j] * CDIM + tid];
    g_weighted[(size_t)b * CDIM + tid] = acc;
}

// ---------------- launch ----------------------------------------------------
extern "C" void kernel_launch(void* const* d_in, const int* in_sizes, int n_in,
                              void* d_out, int out_size) {
    const float* query = (const float*)d_in[0];
    const float* W1    = (const float*)d_in[1];
    const float* b1    = (const float*)d_in[2];
    const float* W2    = (const float*)d_in[3];
    const float* b2    = (const float*)d_in[4];
    const float* W3    = (const float*)d_in[5];
    const float* b3    = (const float*)d_in[6];
    const float* keys  = (const float*)d_in[7];
    const float* values= (const float*)d_in[8];
    const float* D1w   = (const float*)d_in[9];
    const float* D1b   = (const float*)d_in[10];
    const float* D2w   = (const float*)d_in[11];
    const float* D2b   = (const float*)d_in[12];
    const float* D3w   = (const float*)d_in[13];
    const float* D3b   = (const float*)d_in[14];

    float* out  = (float*)d_out;
    float* conf = out + (size_t)BQ * DIM;

    float *p_h1, *p_h2, *p_cq, *p_qn, *p_kn, *p_w, *p_g1, *p_g2;
    cudaGetSymbolAddress((void**)&p_h1, g_h1);
    cudaGetSymbolAddress((void**)&p_h2, g_h2);
    cudaGetSymbolAddress((void**)&p_cq, g_cq);
    cudaGetSymbolAddress((void**)&p_qn, g_qn);
    cudaGetSymbolAddress((void**)&p_kn, g_kn);
    cudaGetSymbolAddress((void**)&p_w,  g_weighted);
    cudaGetSymbolAddress((void**)&p_g1, g_g1);
    cudaGetSymbolAddress((void**)&p_g2, g_g2);

    init_kernel<<<1, 1>>>();

    // Encode MLP: 1024 -> 512 -> 256 -> 128
    sgemm_bias_kernel<1><<<dim3(512 / 64, BQ / 64), 256>>>(query, W1, b1, p_h1, BQ, 512, 1024);
    sgemm_bias_kernel<1><<<dim3(256 / 64, BQ / 64), 256>>>(p_h1, W2, b2, p_h2, BQ, 256, 512);
    sgemm_bias_kernel<0><<<dim3(128 / 64, BQ / 64), 256>>>(p_h2, W3, b3, p_cq, BQ, 128, 256);

    // Norms
    rownorm_kernel<<<(BQ * 32 + 255) / 256, 256>>>(p_cq, p_qn, BQ, 1);
    rownorm_kernel<<<(NKEYS * 32 + 255) / 256, 256>>>(keys, p_kn, NKEYS, 0);

    // Candidate filter (provably covers every query's exact top-5)
    tau_kernel<<<1, 1024>>>();
    cand_kernel<<<(NKEYS + 255) / 256, 256>>>();

    // Exact rescore, top-5, weights, gather, confidence
    rescore_kernel<<<BQ, 128>>>(keys, values, conf);

    // Decode MLP: 128 -> 256 -> 512 -> 1024 (writes retrieved directly to d_out)
    sgemm_bias_kernel<1><<<dim3(256 / 64, BQ / 64), 256>>>(p_w,  D1w, D1b, p_g1, BQ, 256, 128);
    sgemm_bias_kernel<1><<<dim3(512 / 64, BQ / 64), 256>>>(p_g1, D2w, D2b, p_g2, BQ, 512, 256);
    sgemm_bias_kernel<0><<<dim3(1024 / 64, BQ / 64), 256>>>(p_g2, D3w, D3b, out, BQ, 1024, 512);
}

// round 2
// speedup vs baseline: 1.0185x; 1.0185x over previous
#include <cuda_runtime.h>
#include <math.h>

// Problem constants (fixed by setup_inputs)
#define BQ    1024        // batch of queries
#define DIM   1024        // query dim
#define CDIM  128         // compressed dim
#define NKEYS 100000
#define KNN   5
#define EPSW  1e-6f
#define CAP   16384       // candidate capacity (expected ~1000)

// ---------------- scratch (device globals; no allocations allowed) ---------
__device__ float g_h1[BQ * (DIM / 2)];
__device__ float g_h2[BQ * (DIM / 4)];
__device__ float g_cq[BQ * CDIM];
__device__ float g_qn[BQ];
__device__ int   g_Qmax_bits;          // max ||cq||^2 as float bits (>=0)
__device__ float g_kn[NKEYS];
__device__ float g_tau;
__device__ int   g_cand[CAP];
__device__ int   g_cand_count;
__device__ float g_weighted[BQ * CDIM];
__device__ float g_g1[BQ * (DIM / 4)];
__device__ float g_g2[BQ * (DIM / 2)];

// ---------------- small init ----------------------------------------------
__global__ void init_kernel() {
    g_Qmax_bits  = 0;
    g_cand_count = 0;
}

// ---------------- tiled fp32 GEMM: C = act(A[MxK] * B[KxN] + bias) ---------
// BM=BN=64, BK=16, 256 threads, 4x4 per-thread tile. Double-buffered shared
// memory (1 sync per K-tile), global prefetch into registers, 4 blocks/SM.
// All dims are multiples of tile sizes for every layer here (no bounds checks).
template <int RELU>
__global__ __launch_bounds__(256, 4)
void sgemm_bias_kernel(const float* __restrict__ A,
                       const float* __restrict__ Bm,
                       const float* __restrict__ bias,
                       float* __restrict__ Cm,
                       int M, int N, int K) {
    __shared__ float As[2][16][68];   // As[buf][k][m]
    __shared__ float Bs[2][16][68];   // Bs[buf][k][n]
    const int tid = threadIdx.x;
    const int tx = tid & 15;       // n direction
    const int ty = tid >> 4;       // m direction
    const int bm = blockIdx.y * 64, bn = blockIdx.x * 64;

    const int ar = tid >> 2;            // 0..63 (m within tile)
    const int ak = (tid & 3) << 2;      // 0,4,8,12 (k within tile)
    const int br = tid >> 4;            // 0..15 (k within tile)
    const int bc = (tid & 15) << 2;     // 0..60 (n within tile)

    const float* Aptr = A + (size_t)(bm + ar) * K + ak;
    const float* Bptr = Bm + (size_t)br * N + bn + bc;

    // Preload tile 0
    float4 av = *reinterpret_cast<const float4*>(Aptr);
    float4 bv = *reinterpret_cast<const float4*>(Bptr);
    As[0][ak + 0][ar] = av.x;
    As[0][ak + 1][ar] = av.y;
    As[0][ak + 2][ar] = av.z;
    As[0][ak + 3][ar] = av.w;
    *reinterpret_cast<float4*>(&Bs[0][br][bc]) = bv;
    __syncthreads();

    float acc[4][4];
#pragma unroll
    for (int i = 0; i < 4; i++)
#pragma unroll
        for (int j = 0; j < 4; j++) acc[i][j] = 0.f;

    const int nt = K >> 4;
    for (int t = 0; t < nt; t++) {
        const int buf = t & 1;
        if (t + 1 < nt) {  // prefetch next tile from global
            av = *reinterpret_cast<const float4*>(Aptr + (t + 1) * 16);
            bv = *reinterpret_cast<const float4*>(Bptr + (size_t)(t + 1) * 16 * N);
        }
#pragma unroll
        for (int kk = 0; kk < 16; kk++) {
            float4 a4 = *reinterpret_cast<const float4*>(&As[buf][kk][ty * 4]);
            float4 b4 = *reinterpret_cast<const float4*>(&Bs[buf][kk][tx * 4]);
            float aa[4] = {a4.x, a4.y, a4.z, a4.w};
            float bb[4] = {b4.x, b4.y, b4.z, b4.w};
#pragma unroll
            for (int i = 0; i < 4; i++)
#pragma unroll
                for (int j = 0; j < 4; j++)
                    acc[i][j] = fmaf(aa[i], bb[j], acc[i][j]);
        }
        if (t + 1 < nt) {  // stage prefetched tile into the other buffer
            As[buf ^ 1][ak + 0][ar] = av.x;
            As[buf ^ 1][ak + 1][ar] = av.y;
            As[buf ^ 1][ak + 2][ar] = av.z;
            As[buf ^ 1][ak + 3][ar] = av.w;
            *reinterpret_cast<float4*>(&Bs[buf ^ 1][br][bc]) = bv;
            __syncthreads();
        }
    }

    const float4 bvx = *reinterpret_cast<const float4*>(&bias[bn + tx * 4]);
    const float bb4[4] = {bvx.x, bvx.y, bvx.z, bvx.w};
#pragma unroll
    for (int i = 0; i < 4; i++) {
        float4 out;
        float* o = reinterpret_cast<float*>(&out);
#pragma unroll
        for (int j = 0; j < 4; j++) {
            float v = acc[i][j] + bb4[j];
            if (RELU) v = fmaxf(v, 0.f);
            o[j] = v;
        }
        *reinterpret_cast<float4*>(
            &Cm[(size_t)(bm + ty * 4 + i) * N + bn + tx * 4]) = out;
    }
}

// ---------------- row squared-norms (rows of width 128) --------------------
__global__ void rownorm_kernel(const float* __restrict__ X,
                               float* __restrict__ out, int rows, int do_qmax) {
    int gw = (int)((blockIdx.x * (size_t)blockDim.x + threadIdx.x) >> 5);
    int lane = threadIdx.x & 31;
    if (gw >= rows) return;
    float4 v = reinterpret_cast<const float4*>(X + (size_t)gw * 128)[lane];
    float s = v.x * v.x + v.y * v.y + v.z * v.z + v.w * v.w;
#pragma unroll
    for (int o = 16; o; o >>= 1) s += __shfl_xor_sync(0xffffffffu, s, o);
    if (lane == 0) {
        out[gw] = s;
        if (do_qmax) atomicMax(&g_Qmax_bits, __float_as_int(s));  // s >= 0
    }
}

// ---------------- tau = 5th smallest upper bound + margin ------------------
__global__ void tau_kernel() {
    __shared__ float sv[1024 * 5];
    const int tid = threadIdx.x;
    const float Q = sqrtf(__int_as_float(g_Qmax_bits));
    float t5[5] = {3.4e38f, 3.4e38f, 3.4e38f, 3.4e38f, 3.4e38f};
    for (int n = tid; n < NKEYS; n += 1024) {
        float kn = g_kn[n];
        float u = kn + 2.f * Q * sqrtf(kn) + 1e-3f;
        if (u < t5[4]) {
            int p = 4;
            while (p > 0 && t5[p - 1] > u) { t5[p] = t5[p - 1]; p--; }
            t5[p] = u;
        }
    }
#pragma unroll
    for (int i = 0; i < 5; i++) sv[tid * 5 + i] = t5[i];
    __syncthreads();
    for (int stride = 512; stride >= 1; stride >>= 1) {
        if (tid < stride) {
            float a[5], b[5], m[5];
#pragma unroll
            for (int i = 0; i < 5; i++) {
                a[i] = sv[tid * 5 + i];
                b[i] = sv[(tid + stride) * 5 + i];
            }
            int ia = 0, ib = 0;
#pragma unroll
            for (int i = 0; i < 5; i++) m[i] = (a[ia] <= b[ib]) ? a[ia++] : b[ib++];
#pragma unroll
            for (int i = 0; i < 5; i++) sv[tid * 5 + i] = m[i];
        }
        __syncthreads();
    }
    if (tid == 0) g_tau = sv[4] + 1e-2f;
}

// ---------------- candidate compaction -------------------------------------
__global__ void cand_kernel() {
    int n = blockIdx.x * blockDim.x + threadIdx.x;
    if (n >= NKEYS) return;
    float Q = sqrtf(__int_as_float(g_Qmax_bits));
    float kn = g_kn[n];
    float l = kn - 2.f * Q * sqrtf(kn) - 1e-3f;
    if (l <= g_tau) {
        int p = atomicAdd(&g_cand_count, 1);
        if (p < CAP) g_cand[p] = n;
    }
}

// ---------------- exact rescore + top-5 + weighted gather ------------------
#define CHUNK 1024
__global__ void rescore_kernel(const float* __restrict__ keys,
                               const float* __restrict__ values,
                               float* __restrict__ conf_out) {
    const int b = blockIdx.x;      // one query per block
    const int tid = threadIdx.x;   // 128 threads
    __shared__ float sq[CDIM];
    __shared__ float dv[CHUNK];
    __shared__ int   di[CHUNK];
    __shared__ float rd[KNN];
    __shared__ int   ri[KNN];
    __shared__ float rv[128];
    __shared__ int   rvi[128];
    __shared__ int   rvj[128];
    __shared__ float sw[KNN];

    sq[tid] = g_cq[(size_t)b * CDIM + tid];
    if (tid < KNN) { rd[tid] = 3.4e38f; ri[tid] = 0x7fffffff; }
    int count = g_cand_count;
    if (count > CAP) count = CAP;
    __syncthreads();

    for (int c0 = 0; c0 < count; c0 += CHUNK) {
        int len = min(CHUNK, count - c0);
        for (int j = tid; j < len; j += 128) {
            int n = g_cand[c0 + j];
            const float4* kr = reinterpret_cast<const float4*>(keys + (size_t)n * CDIM);
            const float4* sq4 = reinterpret_cast<const float4*>(sq);
            double a0 = 0.0, a1 = 0.0, a2 = 0.0, a3 = 0.0;
#pragma unroll 8
            for (int d = 0; d < CDIM / 4; d++) {
                float4 kv = kr[d];
                float4 qv = sq4[d];
                a0 += (double)qv.x * (double)kv.x;
                a1 += (double)qv.y * (double)kv.y;
                a2 += (double)qv.z * (double)kv.z;
                a3 += (double)qv.w * (double)kv.w;
            }
            double acc = (a0 + a1) + (a2 + a3);
            dv[j] = (float)((double)g_qn[b] + (double)g_kn[n] - 2.0 * acc);
            di[j] = n;
        }
        __syncthreads();
        for (int r = 0; r < KNN; r++) {
            float mv = 3.4e38f; int mi = 0x7fffffff; int mj = -1;
            for (int j = tid; j < len; j += 128) {
                float v = dv[j]; int n = di[j];
                if (v < mv || (v == mv && n < mi)) { mv = v; mi = n; mj = j; }
            }
            rv[tid] = mv; rvi[tid] = mi; rvj[tid] = mj;
            __syncthreads();
            for (int s = 64; s >= 1; s >>= 1) {
                if (tid < s) {
                    if (rv[tid + s] < rv[tid] ||
                        (rv[tid + s] == rv[tid] && rvi[tid + s] < rvi[tid])) {
                        rv[tid] = rv[tid + s];
                        rvi[tid] = rvi[tid + s];
                        rvj[tid] = rvj[tid + s];
                    }
                }
                __syncthreads();
            }
            if (tid == 0 && rvj[0] >= 0) {
                float v = rv[0]; int n = rvi[0];
                if (v < rd[KNN - 1] || (v == rd[KNN - 1] && n < ri[KNN - 1])) {
                    int p = KNN - 1;
                    while (p > 0 && (rd[p - 1] > v ||
                                     (rd[p - 1] == v && ri[p - 1] > n))) {
                        rd[p] = rd[p - 1]; ri[p] = ri[p - 1]; p--;
                    }
                    rd[p] = v; ri[p] = n;
                }
                dv[rvj[0]] = 3.4e38f;  // remove winner from chunk
            }
            __syncthreads();
        }
    }

    if (tid == 0) {
        float w[KNN], ws = 0.f;
#pragma unroll
        for (int j = 0; j < KNN; j++) { w[j] = 1.f / (rd[j] + EPSW); ws += w[j]; }
#pragma unroll
        for (int j = 0; j < KNN; j++) sw[j] = w[j] / ws;
        conf_out[b] = 1.f / (rd[0] + EPSW);
    }
    __syncthreads();

    float acc = 0.f;
#pragma unroll
    for (int j = 0; j < KNN; j++)
        acc += sw[j] * values[(size_t)ri[j] * CDIM + tid];
    g_weighted[(size_t)b * CDIM + tid] = acc;
}

// ---------------- launch ----------------------------------------------------
extern "C" void kernel_launch(void* const* d_in, const int* in_sizes, int n_in,
                              void* d_out, int out_size) {
    const float* query = (const float*)d_in[0];
    const float* W1    = (const float*)d_in[1];
    const float* b1    = (const float*)d_in[2];
    const float* W2    = (const float*)d_in[3];
    const float* b2    = (const float*)d_in[4];
    const float* W3    = (const float*)d_in[5];
    const float* b3    = (const float*)d_in[6];
    const float* keys  = (const float*)d_in[7];
    const float* values= (const float*)d_in[8];
    const float* D1w   = (const float*)d_in[9];
    const float* D1b   = (const float*)d_in[10];
    const float* D2w   = (const float*)d_in[11];
    const float* D2b   = (const float*)d_in[12];
    const float* D3w   = (const float*)d_in[13];
    const float* D3b   = (const float*)d_in[14];

    float* out  = (float*)d_out;
    float* conf = out + (size_t)BQ * DIM;

    float *p_h1, *p_h2, *p_cq, *p_qn, *p_kn, *p_w, *p_g1, *p_g2;
    cudaGetSymbolAddress((void**)&p_h1, g_h1);
    cudaGetSymbolAddress((void**)&p_h2, g_h2);
    cudaGetSymbolAddress((void**)&p_cq, g_cq);
    cudaGetSymbolAddress((void**)&p_qn, g_qn);
    cudaGetSymbolAddress((void**)&p_kn, g_kn);
    cudaGetSymbolAddress((void**)&p_w,  g_weighted);
    cudaGetSymbolAddress((void**)&p_g1, g_g1);
    cudaGetSymbolAddress((void**)&p_g2, g_g2);

    init_kernel<<<1, 1>>>();

    // Key norms (independent of encode chain; issue early)
    rownorm_kernel<<<(NKEYS * 32 + 255) / 256, 256>>>(keys, p_kn, NKEYS, 0);

    // Encode MLP: 1024 -> 512 -> 256 -> 128
    sgemm_bias_kernel<1><<<dim3(512 / 64, BQ / 64), 256>>>(query, W1, b1, p_h1, BQ, 512, 1024);
    sgemm_bias_kernel<1><<<dim3(256 / 64, BQ / 64), 256>>>(p_h1, W2, b2, p_h2, BQ, 256, 512);
    sgemm_bias_kernel<0><<<dim3(128 / 64, BQ / 64), 256>>>(p_h2, W3, b3, p_cq, BQ, 128, 256);

    // Query norms + Qmax
    rownorm_kernel<<<(BQ * 32 + 255) / 256, 256>>>(p_cq, p_qn, BQ, 1);

    // Candidate filter (provably covers every query's exact top-5)
    tau_kernel<<<1, 1024>>>();
    cand_kernel<<<(NKEYS + 255) / 256, 256>>>();

    // Exact rescore, top-5, weights, gather, confidence
    rescore_kernel<<<BQ, 128>>>(keys, values, conf);

    // Decode MLP: 128 -> 256 -> 512 -> 1024 (writes retrieved directly to d_out)
    sgemm_bias_kernel<1><<<dim3(256 / 64, BQ / 64), 256>>>(p_w,  D1w, D1b, p_g1, BQ, 256, 128);
    sgemm_bias_kernel<1><<<dim3(512 / 64, BQ / 64), 256>>>(p_g1, D2w, D2b, p_g2, BQ, 512, 256);
    sgemm_bias_kernel<0><<<dim3(1024 / 64, BQ / 64), 256>>>(p_g2, D3w, D3b, out, BQ, 1024, 512);
}

// round 3
// speedup vs baseline: 8.6809x; 8.5231x over previous
#include <cuda_runtime.h>
#include <math.h>
#include <float.h>

// Problem constants (fixed by setup_inputs)
#define BQ    1024        // batch of queries
#define DIM   1024        // query dim
#define CDIM  128         // compressed dim
#define NKEYS 100000
#define KNN   5
#define EPSW  1e-6f
#define CAP   49152       // candidate capacity
#define NB    2048        // kn buckets

// ---------------- scratch (device globals; no allocations allowed) ---------
__device__ float g_h1[BQ * (DIM / 2)];
__device__ float g_h2[BQ * (DIM / 4)];
__device__ float g_cq[BQ * CDIM];
__device__ float g_qn[BQ];
__device__ int   g_Qmax_bits;          // max ||cq||^2 as float bits (>=0)
__device__ float g_kn[NKEYS];
__device__ float g_tau;
__device__ float g_invw;               // NB / hi  (bucket mapping)
__device__ float g_w;                  // hi / NB
__device__ int   g_hist[NB];
__device__ int   g_cursor[NB];
__device__ int   g_cand_count;
__device__ int   g_scand[CAP];         // candidate key indices, bucket-sorted by kn
__device__ float g_skn[CAP];           // kn of sorted candidates
__device__ float g_sblo[CAP];          // safe lower bound on kn for pos..end
__device__ float g_weighted[BQ * CDIM];
__device__ float g_g1[BQ * (DIM / 4)];
__device__ float g_g2[BQ * (DIM / 2)];

// ---------------- init ------------------------------------------------------
__global__ void init_kernel() {
    int t = blockIdx.x * blockDim.x + threadIdx.x;
    if (t == 0) { g_Qmax_bits = 0; g_cand_count = 0; }
    if (t < NB) g_hist[t] = 0;
}

// ---------------- tiled fp32 GEMM: C = act(A[MxK] * B[KxN] + bias) ---------
template <int RELU>
__global__ __launch_bounds__(256, 4)
void sgemm_bias_kernel(const float* __restrict__ A,
                       const float* __restrict__ Bm,
                       const float* __restrict__ bias,
                       float* __restrict__ Cm,
                       int M, int N, int K) {
    __shared__ float As[2][16][68];   // As[buf][k][m]
    __shared__ float Bs[2][16][68];   // Bs[buf][k][n]
    const int tid = threadIdx.x;
    const int tx = tid & 15;
    const int ty = tid >> 4;
    const int bm = blockIdx.y * 64, bn = blockIdx.x * 64;

    const int ar = tid >> 2;
    const int ak = (tid & 3) << 2;
    const int br = tid >> 4;
    const int bc = (tid & 15) << 2;

    const float* Aptr = A + (size_t)(bm + ar) * K + ak;
    const float* Bptr = Bm + (size_t)br * N + bn + bc;

    float4 av = *reinterpret_cast<const float4*>(Aptr);
    float4 bv = *reinterpret_cast<const float4*>(Bptr);
    As[0][ak + 0][ar] = av.x;
    As[0][ak + 1][ar] = av.y;
    As[0][ak + 2][ar] = av.z;
    As[0][ak + 3][ar] = av.w;
    *reinterpret_cast<float4*>(&Bs[0][br][bc]) = bv;
    __syncthreads();

    float acc[4][4];
#pragma unroll
    for (int i = 0; i < 4; i++)
#pragma unroll
        for (int j = 0; j < 4; j++) acc[i][j] = 0.f;

    const int nt = K >> 4;
    for (int t = 0; t < nt; t++) {
        const int buf = t & 1;
        if (t + 1 < nt) {
            av = *reinterpret_cast<const float4*>(Aptr + (t + 1) * 16);
            bv = *reinterpret_cast<const float4*>(Bptr + (size_t)(t + 1) * 16 * N);
        }
#pragma unroll
        for (int kk = 0; kk < 16; kk++) {
            float4 a4 = *reinterpret_cast<const float4*>(&As[buf][kk][ty * 4]);
            float4 b4 = *reinterpret_cast<const float4*>(&Bs[buf][kk][tx * 4]);
            float aa[4] = {a4.x, a4.y, a4.z, a4.w};
            float bb[4] = {b4.x, b4.y, b4.z, b4.w};
#pragma unroll
            for (int i = 0; i < 4; i++)
#pragma unroll
                for (int j = 0; j < 4; j++)
                    acc[i][j] = fmaf(aa[i], bb[j], acc[i][j]);
        }
        if (t + 1 < nt) {
            As[buf ^ 1][ak + 0][ar] = av.x;
            As[buf ^ 1][ak + 1][ar] = av.y;
            As[buf ^ 1][ak + 2][ar] = av.z;
            As[buf ^ 1][ak + 3][ar] = av.w;
            *reinterpret_cast<float4*>(&Bs[buf ^ 1][br][bc]) = bv;
            __syncthreads();
        }
    }

    const float4 bvx = *reinterpret_cast<const float4*>(&bias[bn + tx * 4]);
    const float bb4[4] = {bvx.x, bvx.y, bvx.z, bvx.w};
#pragma unroll
    for (int i = 0; i < 4; i++) {
        float4 out;
        float* o = reinterpret_cast<float*>(&out);
#pragma unroll
        for (int j = 0; j < 4; j++) {
            float v = acc[i][j] + bb4[j];
            if (RELU) v = fmaxf(v, 0.f);
            o[j] = v;
        }
        *reinterpret_cast<float4*>(
            &Cm[(size_t)(bm + ty * 4 + i) * N + bn + tx * 4]) = out;
    }
}

// ---------------- row squared-norms (rows of width 128) --------------------
__global__ void rownorm_kernel(const float* __restrict__ X,
                               float* __restrict__ out, int rows, int do_qmax) {
    int gw = (int)((blockIdx.x * (size_t)blockDim.x + threadIdx.x) >> 5);
    int lane = threadIdx.x & 31;
    if (gw >= rows) return;
    float4 v = reinterpret_cast<const float4*>(X + (size_t)gw * 128)[lane];
    float s = v.x * v.x + v.y * v.y + v.z * v.z + v.w * v.w;
#pragma unroll
    for (int o = 16; o; o >>= 1) s += __shfl_xor_sync(0xffffffffu, s, o);
    if (lane == 0) {
        out[gw] = s;
        if (do_qmax) atomicMax(&g_Qmax_bits, __float_as_int(s));  // s >= 0
    }
}

// ---------------- tau = 5th smallest upper bound + bucket params -----------
__global__ void tau_kernel() {
    __shared__ float sv[1024 * 5];
    const int tid = threadIdx.x;
    const float Q = sqrtf(__int_as_float(g_Qmax_bits));
    float t5[5] = {3.4e38f, 3.4e38f, 3.4e38f, 3.4e38f, 3.4e38f};
    for (int n = tid; n < NKEYS; n += 1024) {
        float kn = g_kn[n];
        float u = kn + 2.f * Q * sqrtf(kn) + 1e-3f;
        if (u < t5[4]) {
            int p = 4;
            while (p > 0 && t5[p - 1] > u) { t5[p] = t5[p - 1]; p--; }
            t5[p] = u;
        }
    }
#pragma unroll
    for (int i = 0; i < 5; i++) sv[tid * 5 + i] = t5[i];
    __syncthreads();
    for (int stride = 512; stride >= 1; stride >>= 1) {
        if (tid < stride) {
            float a[5], b[5], m[5];
#pragma unroll
            for (int i = 0; i < 5; i++) {
                a[i] = sv[tid * 5 + i];
                b[i] = sv[(tid + stride) * 5 + i];
            }
            int ia = 0, ib = 0;
#pragma unroll
            for (int i = 0; i < 5; i++) m[i] = (a[ia] <= b[ib]) ? a[ia++] : b[ib++];
#pragma unroll
            for (int i = 0; i < 5; i++) sv[tid * 5 + i] = m[i];
        }
        __syncthreads();
    }
    if (tid == 0) {
        float tau = sv[4] + 1e-2f;
        g_tau = tau;
        // all candidates have kn <= (Q + sqrt(Q^2 + tau))^2 (+slack)
        float r = Q + sqrtf(Q * Q + tau);
        float hi = r * r * 1.02f + 1.f;
        g_invw = (float)NB / hi;
        g_w = hi / (float)NB;
    }
}

// ---------------- pass 1: histogram candidates by kn bucket -----------------
__global__ void cand_hist_kernel() {
    int n = blockIdx.x * blockDim.x + threadIdx.x;
    if (n >= NKEYS) return;
    float Q = sqrtf(__int_as_float(g_Qmax_bits));
    float kn = g_kn[n];
    float l = kn - 2.f * Q * sqrtf(kn) - 1e-3f;
    if (l <= g_tau) {
        int b = min(NB - 1, (int)(kn * g_invw));
        atomicAdd(&g_hist[b], 1);
    }
}

// ---------------- exclusive scan over NB buckets (one block) ----------------
__global__ void scan_kernel() {
    __shared__ int s[NB];
    __shared__ int tmp[NB];
    const int tid = threadIdx.x;   // 1024
    for (int i = tid; i < NB; i += 1024) s[i] = g_hist[i];
    __syncthreads();
    for (int off = 1; off < NB; off <<= 1) {
        for (int i = tid; i < NB; i += 1024)
            tmp[i] = s[i] + (i >= off ? s[i - off] : 0);
        __syncthreads();
        for (int i = tid; i < NB; i += 1024) s[i] = tmp[i];
        __syncthreads();
    }
    for (int i = tid; i < NB; i += 1024)
        g_cursor[i] = (i == 0) ? 0 : s[i - 1];   // exclusive prefix
    if (tid == 0) g_cand_count = s[NB - 1];
}

// ---------------- pass 2: scatter into bucket-sorted arrays -----------------
__global__ void scatter_kernel() {
    int n = blockIdx.x * blockDim.x + threadIdx.x;
    if (n >= NKEYS) return;
    float Q = sqrtf(__int_as_float(g_Qmax_bits));
    float kn = g_kn[n];
    float l = kn - 2.f * Q * sqrtf(kn) - 1e-3f;
    if (l <= g_tau) {
        int b = min(NB - 1, (int)(kn * g_invw));
        int pos = atomicAdd(&g_cursor[b], 1);
        if (pos < CAP) {
            g_scand[pos] = n;
            g_skn[pos]   = kn;
            g_sblo[pos]  = (float)b * g_w;  // kn >= this for all positions >= pos
        }
    }
}

// ---------------- exact rescore + top-5 + weighted gather ------------------
// One query per block, 128 threads. Candidates are bucket-sorted by kn, so we
// scan chunks of 128 with a provably safe early exit:
//   d2(n) >= qn + kn - 2*qb*sqrt(kn) >= qn + f(blo)  (f increasing for kn>qb^2)
__global__ __launch_bounds__(128, 8)
void rescore_kernel(const float* __restrict__ keys,
                    const float* __restrict__ values,
                    float* __restrict__ conf_out) {
    const int b = blockIdx.x;
    const int tid = threadIdx.x;
    __shared__ float sq[CDIM];
    __shared__ float dv[128];
    __shared__ int   di[128];
    __shared__ float rd[KNN];
    __shared__ int   ri[KNN];
    __shared__ float rv[128];
    __shared__ int   rvi[128];
    __shared__ int   rvj[128];
    __shared__ float sw[KNN];
    __shared__ int   s_stop;

    sq[tid] = g_cq[(size_t)b * CDIM + tid];
    if (tid < KNN) { rd[tid] = 3.4e38f; ri[tid] = 0x7fffffff; }
    if (tid == 0) s_stop = 0;
    int count = g_cand_count;
    if (count > CAP) count = CAP;
    const float qn = g_qn[b];
    const float qb = sqrtf(qn);
    __syncthreads();

    for (int c0 = 0; c0 < count; c0 += 128) {
        // early exit: min possible d2 among remaining candidates
        if (tid == 0 && c0 > 0) {
            float blo = g_sblo[c0];
            float lb = qn + blo - 2.f * qb * sqrtf(blo) - 1e-3f;
            if (lb > rd[KNN - 1]) s_stop = 1;
        }
        __syncthreads();
        if (s_stop) break;

        int len = min(128, count - c0);
        int j = c0 + tid;
        if (tid < len) {
            int n = g_scand[j];
            const float4* kr = reinterpret_cast<const float4*>(keys + (size_t)n * CDIM);
            const float4* sq4 = reinterpret_cast<const float4*>(sq);
            float a0 = 0.f, a1 = 0.f, a2 = 0.f, a3 = 0.f;
#pragma unroll
            for (int d = 0; d < CDIM / 4; d++) {
                float4 kv = __ldg(&kr[d]);
                float4 qv = sq4[d];
                a0 = fmaf(qv.x, kv.x, a0);
                a1 = fmaf(qv.y, kv.y, a1);
                a2 = fmaf(qv.z, kv.z, a2);
                a3 = fmaf(qv.w, kv.w, a3);
            }
            float dot = (a0 + a1) + (a2 + a3);
            dv[tid] = qn + g_skn[j] - 2.f * dot;
            di[tid] = n;
        } else {
            dv[tid] = 3.4e38f;
            di[tid] = 0x7fffffff;
        }
        __syncthreads();

        for (int r = 0; r < KNN; r++) {
            rv[tid] = dv[tid]; rvi[tid] = di[tid]; rvj[tid] = tid;
            __syncthreads();
#pragma unroll
            for (int s = 64; s >= 1; s >>= 1) {
                if (tid < s) {
                    if (rv[tid + s] < rv[tid] ||
                        (rv[tid + s] == rv[tid] && rvi[tid + s] < rvi[tid])) {
                        rv[tid] = rv[tid + s];
                        rvi[tid] = rvi[tid + s];
                        rvj[tid] = rvj[tid + s];
                    }
                }
                __syncthreads();
            }
            if (tid == 0) {
                float v = rv[0]; int n = rvi[0];
                if (v < rd[KNN - 1] || (v == rd[KNN - 1] && n < ri[KNN - 1])) {
                    int p = KNN - 1;
                    while (p > 0 && (rd[p - 1] > v ||
                                     (rd[p - 1] == v && ri[p - 1] > n))) {
                        rd[p] = rd[p - 1]; ri[p] = ri[p - 1]; p--;
                    }
                    rd[p] = v; ri[p] = n;
                }
                dv[rvj[0]] = 3.4e38f;  // remove winner from chunk
            }
            __syncthreads();
        }
    }

    if (tid == 0) {
        float w[KNN], ws = 0.f;
#pragma unroll
        for (int j2 = 0; j2 < KNN; j2++) { w[j2] = 1.f / (rd[j2] + EPSW); ws += w[j2]; }
#pragma unroll
        for (int j2 = 0; j2 < KNN; j2++) sw[j2] = w[j2] / ws;
        conf_out[b] = 1.f / (rd[0] + EPSW);
    }
    __syncthreads();

    float acc = 0.f;
#pragma unroll
    for (int j2 = 0; j2 < KNN; j2++)
        acc += sw[j2] * values[(size_t)ri[j2] * CDIM + tid];
    g_weighted[(size_t)b * CDIM + tid] = acc;
}

// ---------------- launch ----------------------------------------------------
extern "C" void kernel_launch(void* const* d_in, const int* in_sizes, int n_in,
                              void* d_out, int out_size) {
    const float* query = (const float*)d_in[0];
    const float* W1    = (const float*)d_in[1];
    const float* b1    = (const float*)d_in[2];
    const float* W2    = (const float*)d_in[3];
    const float* b2    = (const float*)d_in[4];
    const float* W3    = (const float*)d_in[5];
    const float* b3    = (const float*)d_in[6];
    const float* keys  = (const float*)d_in[7];
    const float* values= (const float*)d_in[8];
    const float* D1w   = (const float*)d_in[9];
    const float* D1b   = (const float*)d_in[10];
    const float* D2w   = (const float*)d_in[11];
    const float* D2b   = (const float*)d_in[12];
    const float* D3w   = (const float*)d_in[13];
    const float* D3b   = (const float*)d_in[14];

    float* out  = (float*)d_out;
    float* conf = out + (size_t)BQ * DIM;

    float *p_h1, *p_h2, *p_cq, *p_qn, *p_kn, *p_w, *p_g1, *p_g2;
    cudaGetSymbolAddress((void**)&p_h1, g_h1);
    cudaGetSymbolAddress((void**)&p_h2, g_h2);
    cudaGetSymbolAddress((void**)&p_cq, g_cq);
    cudaGetSymbolAddress((void**)&p_qn, g_qn);
    cudaGetSymbolAddress((void**)&p_kn, g_kn);
    cudaGetSymbolAddress((void**)&p_w,  g_weighted);
    cudaGetSymbolAddress((void**)&p_g1, g_g1);
    cudaGetSymbolAddress((void**)&p_g2, g_g2);

    init_kernel<<<NB / 256, 256>>>();

    // Key norms (independent of encode chain; issue early)
    rownorm_kernel<<<(NKEYS * 32 + 255) / 256, 256>>>(keys, p_kn, NKEYS, 0);

    // Encode MLP: 1024 -> 512 -> 256 -> 128
    sgemm_bias_kernel<1><<<dim3(512 / 64, BQ / 64), 256>>>(query, W1, b1, p_h1, BQ, 512, 1024);
    sgemm_bias_kernel<1><<<dim3(256 / 64, BQ / 64), 256>>>(p_h1, W2, b2, p_h2, BQ, 256, 512);
    sgemm_bias_kernel<0><<<dim3(128 / 64, BQ / 64), 256>>>(p_h2, W3, b3, p_cq, BQ, 128, 256);

    // Query norms + Qmax
    rownorm_kernel<<<(BQ * 32 + 255) / 256, 256>>>(p_cq, p_qn, BQ, 1);

    // Candidate filter -> bucket-sorted candidate list
    tau_kernel<<<1, 1024>>>();
    cand_hist_kernel<<<(NKEYS + 255) / 256, 256>>>();
    scan_kernel<<<1, 1024>>>();
    scatter_kernel<<<(NKEYS + 255) / 256, 256>>>();

    // Exact rescore (fp32) with safe early exit, top-5, weights, gather
    rescore_kernel<<<BQ, 128>>>(keys, values, conf);

    // Decode MLP: 128 -> 256 -> 512 -> 1024 (writes retrieved directly to d_out)
    sgemm_bias_kernel<1><<<dim3(256 / 64, BQ / 64), 256>>>(p_w,  D1w, D1b, p_g1, BQ, 256, 128);
    sgemm_bias_kernel<1><<<dim3(512 / 64, BQ / 64), 256>>>(p_g1, D2w, D2b, p_g2, BQ, 512, 256);
    sgemm_bias_kernel<0><<<dim3(1024 / 64, BQ / 64), 256>>>(p_g2, D3w, D3b, out, BQ, 1024, 512);
}